// round 16
// baseline (speedup 1.0000x reference)
#include <cuda_runtime.h>
#include <cuda_bf16.h>
#include <math.h>
#include <cstdint>

#define B_ 4096
#define D_ 256
#define NPROTO 256

// ---------------- scratch (device globals; no allocations allowed) ----------------
__device__ __nv_bfloat16 g_h1bf[(size_t)B_ * 225 * 32];   // NHWC bf16
__device__ __nv_bfloat16 g_h2bf[(size_t)B_ * 64 * 64];    // NHWC bf16
__device__ __nv_bfloat16 g_h3bf[(size_t)B_ * 64 * 128];   // NHWC bf16
__device__ __nv_bfloat16 g_h4bf[(size_t)B_ * 64 * 256];   // NHWC bf16
__device__ float g_z0[B_ * D_];
__device__ float g_z[B_ * D_];
__device__ float g_protosT[NPROTO * D_];
__device__ float g_gridT[NPROTO * D_];
__device__ float g_pn2[NPROTO];
__device__ float g_gn2[NPROTO];
__device__ float g_wsum[D_ * 10];
__device__ __nv_bfloat16 g_encwT[(size_t)D_ * 16384];   // [d][k], k = p*256+c
__device__ __nv_bfloat16 g_w2t[9 * 64 * 32];            // [tap][oc][c]
__device__ __nv_bfloat16 g_w3t[9 * 128 * 64];
__device__ __nv_bfloat16 g_w4t[9 * 256 * 128];

// ================= helpers =================
__device__ __forceinline__ uint32_t smem_u32(const void* p) {
    uint32_t a;
    asm("{ .reg .u64 t; cvta.to.shared.u64 t, %1; cvt.u32.u64 %0, t; }" : "=r"(a) : "l"(p));
    return a;
}
__device__ __forceinline__ void cp16(uint32_t s, const void* g) {
    asm volatile("cp.async.cg.shared.global [%0], [%1], 16;" :: "r"(s), "l"(g));
}
#define CP_COMMIT() asm volatile("cp.async.commit_group;" ::: "memory")
#define CP_WAIT1()  asm volatile("cp.async.wait_group 1;" ::: "memory")
#define CP_WAIT0()  asm volatile("cp.async.wait_group 0;" ::: "memory")

__device__ __forceinline__ uint32_t packbf(float lo, float hi) {
    uint32_t r; asm("cvt.rn.bf16x2.f32 %0, %1, %2;" : "=r"(r) : "f"(hi), "f"(lo)); return r;
}
__device__ __forceinline__ void mma16(float c[4], const uint32_t a[4], const uint32_t b[2]) {
    asm volatile(
        "mma.sync.aligned.m16n8k16.row.col.f32.bf16.bf16.f32 "
        "{%0,%1,%2,%3}, {%4,%5,%6,%7}, {%8,%9}, {%0,%1,%2,%3};"
        : "+f"(c[0]), "+f"(c[1]), "+f"(c[2]), "+f"(c[3])
        : "r"(a[0]), "r"(a[1]), "r"(a[2]), "r"(a[3]), "r"(b[0]), "r"(b[1]));
}
__device__ __forceinline__ void ldsm_x4(uint32_t r[4], uint32_t addr) {
    asm volatile("ldmatrix.sync.aligned.m8n8.x4.shared.b16 {%0,%1,%2,%3}, [%4];"
        : "=r"(r[0]), "=r"(r[1]), "=r"(r[2]), "=r"(r[3]) : "r"(addr));
}
__device__ __forceinline__ void ldsm_x2(uint32_t r[2], uint32_t addr) {
    asm volatile("ldmatrix.sync.aligned.m8n8.x2.shared.b16 {%0,%1}, [%2];"
        : "=r"(r[0]), "=r"(r[1]) : "r"(addr));
}

// ================= merged prep kernel =================
__global__ void prep_all(const float* __restrict__ protos,
                         const float* __restrict__ grid_pos,
                         const float* __restrict__ clf_w,
                         const float* __restrict__ enc_w,
                         const float* __restrict__ w2,
                         const float* __restrict__ w3,
                         const float* __restrict__ w4) {
    __shared__ float sbuf[32 * 257];
    int bid = blockIdx.x;
    int tid = threadIdx.x;
    if (bid < 256) {
        float pv = protos[bid * D_ + tid];
        float gv = grid_pos[bid * D_ + tid];
        g_protosT[tid * NPROTO + bid] = pv;
        g_gridT[tid * NPROTO + bid] = gv;
        float* red = sbuf;
        red[tid] = pv * pv;
        __syncthreads();
        for (int s = 128; s > 0; s >>= 1) { if (tid < s) red[tid] += red[tid + s]; __syncthreads(); }
        if (tid == 0) g_pn2[bid] = red[0];
        __syncthreads();
        red[tid] = gv * gv;
        __syncthreads();
        for (int s = 128; s > 0; s >>= 1) { if (tid < s) red[tid] += red[tid + s]; __syncthreads(); }
        if (tid == 0) g_gn2[bid] = red[0];
    } else if (bid == 256) {
        for (int i = tid; i < D_ * 10; i += 256) {
            int dd = i / 10, c = i % 10;
            float s = 0.f;
            #pragma unroll
            for (int h = 0; h < 4; h++) s += clf_w[(h * 256 + dd) * 10 + c];
            g_wsum[i] = s;
        }
    } else if (bid < 769) {
        float (*s)[257] = (float (*)[257])sbuf;
        int k0 = (bid - 257) * 32;
        for (int r = 0; r < 32; r++) {
            int k = k0 + r;
            int c = k & 255, p = k >> 8;
            s[r][tid] = enc_w[(size_t)(c * 64 + p) * 256 + tid];
        }
        __syncthreads();
        int lane = tid & 31, w = tid >> 5;
        for (int d = w; d < 256; d += 8)
            g_encwT[(size_t)d * 16384 + k0 + lane] = __float2bfloat16(s[lane][d]);
    } else {
        const float* w; __nv_bfloat16* wt; int COUT, CIN, base;
        if (bid < 841)       { w = w2; wt = g_w2t; COUT = 64;  CIN = 32;  base = 769; }
        else if (bid < 1129) { w = w3; wt = g_w3t; COUT = 128; CIN = 64;  base = 841; }
        else                 { w = w4; wt = g_w4t; COUT = 256; CIN = 128; base = 1129; }
        int i = (bid - base) * 256 + tid;
        if (i < 9 * COUT * CIN) {
            int c = i % CIN;
            int oc = (i / CIN) % COUT;
            int t = i / (CIN * COUT);
            wt[i] = __float2bfloat16(w[((size_t)(oc * CIN + c)) * 9 + t]);
        }
    }
}

// ================= conv1: 3->32, 5x5, s2, p1 — branch-free padded, reg weights =================
__global__ __launch_bounds__(256) void conv1_kernel(const float* __restrict__ x,
                                                    const float* __restrict__ w,
                                                    const float* __restrict__ bias) {
    __shared__ __align__(16) float xs[3 * 34 * 36];
    __shared__ float ws[2400];
    int b = blockIdx.x, tid = threadIdx.x;
    for (int i = tid; i < 3 * 34 * 36; i += 256) xs[i] = 0.f;
    for (int i = tid; i < 2400; i += 256) ws[i] = w[i];
    __syncthreads();
    const float* xb = x + (size_t)b * 3072;
    for (int i = tid; i < 3072; i += 256) {
        int c = i >> 10, rem = i & 1023, ih = rem >> 5, iw = rem & 31;
        xs[c * 1224 + (ih + 1) * 36 + (iw + 1)] = xb[i];
    }
    __syncthreads();
    int oc = tid & 31, wg = tid >> 5;
    float wr[75];
    #pragma unroll
    for (int t = 0; t < 75; t++) wr[t] = ws[oc * 75 + t];
    float bv = bias[oc];
    __nv_bfloat16* ob = g_h1bf + (size_t)b * 225 * 32 + oc;
    for (int oh = wg; oh < 15; oh += 8) {
        float acc[8];
        #pragma unroll
        for (int j = 0; j < 8; j++) acc[j] = bv;
        #pragma unroll
        for (int c = 0; c < 3; c++)
            #pragma unroll
            for (int kh = 0; kh < 5; kh++) {
                const float* row = xs + c * 1224 + (2 * oh + kh) * 36;
                float xv[20];
                #pragma unroll
                for (int q = 0; q < 5; q++) *(float4*)(xv + q * 4) = *(const float4*)(row + q * 4);
                #pragma unroll
                for (int kw = 0; kw < 5; kw++) {
                    float wv = wr[c * 25 + kh * 5 + kw];
                    #pragma unroll
                    for (int ow = 0; ow < 8; ow++) acc[ow] += xv[2 * ow + kw] * wv;
                }
            }
        #pragma unroll
        for (int ow = 0; ow < 8; ow++)
            ob[(size_t)(oh * 15 + ow) * 32] = __float2bfloat16(fmaxf(acc[ow], 0.f));
        float acc2[7];
        #pragma unroll
        for (int j = 0; j < 7; j++) acc2[j] = bv;
        #pragma unroll
        for (int c = 0; c < 3; c++)
            #pragma unroll
            for (int kh = 0; kh < 5; kh++) {
                const float* row = xs + c * 1224 + (2 * oh + kh) * 36 + 16;
                float xv[20];
                #pragma unroll
                for (int q = 0; q < 5; q++) *(float4*)(xv + q * 4) = *(const float4*)(row + q * 4);
                #pragma unroll
                for (int kw = 0; kw < 5; kw++) {
                    float wv = wr[c * 25 + kh * 5 + kw];
                    #pragma unroll
                    for (int j = 0; j < 7; j++) acc2[j] += xv[2 * j + kw] * wv;
                }
            }
        #pragma unroll
        for (int j = 0; j < 7; j++)
            ob[(size_t)(oh * 15 + 8 + j) * 32] = __float2bfloat16(fmaxf(acc2[j], 0.f));
    }
}

// ================= conv2 mma: 32->64, 3x3, s2, p1 — spatially padded 17x17 RAW =================
__global__ __launch_bounds__(256, 2) void conv2_mma(const __nv_bfloat16* __restrict__ in,
                                                    const __nv_bfloat16* __restrict__ wt,
                                                    const float* __restrict__ bias,
                                                    __nv_bfloat16* __restrict__ out) {
    extern __shared__ char dynsm[];
    __nv_bfloat16* RAW = (__nv_bfloat16*)dynsm;            // 2*289*40
    __nv_bfloat16* BS = RAW + 2 * 289 * 40;                // 3*64*40
    uint32_t rawb = smem_u32(RAW), bsb = smem_u32(BS);
    int tid = threadIdx.x, lane = tid & 31, wid = tid >> 5;
    int mwarp = wid & 1, nwarp = wid >> 1;
    int b0 = blockIdx.x * 2;

    uint4 z4 = make_uint4(0, 0, 0, 0);
    for (int i = tid; i < 2890; i += 256) ((uint4*)RAW)[i] = z4;
    __syncthreads();

    const __nv_bfloat16* inb = in + (size_t)b0 * 225 * 32;
    for (int i = tid; i < 1800; i += 256) {
        int img = i / 900, rem = i % 900, px = rem >> 2, seg = rem & 3;
        int ih = px / 15, iw = px % 15;
        int pad = img * 289 + (ih + 1) * 17 + (iw + 1);
        cp16(rawb + (uint32_t)((pad * 40 + seg * 8) * 2),
             inb + (size_t)(img * 225 + px) * 32 + seg * 8);
    }
    auto issueB = [&](int j) {
        int oc = tid >> 2, seg = tid & 3;
        cp16(bsb + (uint32_t)((j % 3) * 64 * 40 + oc * 40 + seg * 8) * 2,
             wt + ((size_t)j * 64 + oc) * 32 + seg * 8);
    };
    issueB(0); CP_COMMIT();
    issueB(1); CP_COMMIT();

    int tile_r = lane & 15, khalf = lane >> 4;
    uint32_t abase[4];
    #pragma unroll
    for (int mt = 0; mt < 4; mt++) {
        int r = mwarp * 64 + mt * 16 + tile_r;
        int img = r >> 6, px = r & 63, oh = px >> 3, ow = px & 7;
        int pad = img * 289 + (2 * oh) * 17 + (2 * ow);
        abase[mt] = rawb + (uint32_t)((pad * 40 + khalf * 8) * 2);
    }
    int nB = nwarp * 16 + (lane & 7);
    int khB = (lane >> 3) & 1;

    float acc[4][2][4];
    #pragma unroll
    for (int mt = 0; mt < 4; mt++)
        #pragma unroll
        for (int nt = 0; nt < 2; nt++)
            #pragma unroll
            for (int q = 0; q < 4; q++) acc[mt][nt][q] = 0.f;

    for (int i = 0; i < 9; i++) {
        CP_WAIT1();
        __syncthreads();
        if (i + 2 < 9) { issueB(i + 2); }
        CP_COMMIT();
        int kh = i / 3, kw = i % 3;
        uint32_t toff = (uint32_t)(((kh * 17 + kw) * 40) * 2);
        uint32_t aaddr[4];
        #pragma unroll
        for (int mt = 0; mt < 4; mt++) aaddr[mt] = abase[mt] + toff;
        uint32_t bbase = bsb + (uint32_t)((i % 3) * 64 * 40 * 2);
        #pragma unroll
        for (int kk = 0; kk < 2; kk++) {
            uint32_t a[4][4];
            #pragma unroll
            for (int mt = 0; mt < 4; mt++) ldsm_x4(a[mt], aaddr[mt] + kk * 32);
            uint32_t b[2][2];
            #pragma unroll
            for (int nt = 0; nt < 2; nt++)
                ldsm_x2(b[nt], bbase + (uint32_t)(((nB + nt * 8) * 40 + kk * 16 + khB * 8) * 2));
            #pragma unroll
            for (int mt = 0; mt < 4; mt++)
                #pragma unroll
                for (int nt = 0; nt < 2; nt++)
                    mma16(acc[mt][nt], a[mt], b[nt]);
        }
    }
    #pragma unroll
    for (int mt = 0; mt < 4; mt++)
        #pragma unroll
        for (int nt = 0; nt < 2; nt++) {
            int n = nwarp * 16 + nt * 8 + (lane & 3) * 2;
            float bv0 = bias[n], bv1 = bias[n + 1];
            #pragma unroll
            for (int h = 0; h < 2; h++) {
                int r = mwarp * 64 + mt * 16 + (lane >> 2) + h * 8;
                int img = r >> 6, px = r & 63;
                uint32_t pk = packbf(fmaxf(acc[mt][nt][h * 2 + 0] + bv0, 0.f),
                                     fmaxf(acc[mt][nt][h * 2 + 1] + bv1, 0.f));
                *(uint32_t*)(out + ((size_t)(b0 + img) * 64 + px) * 64 + n) = pk;
            }
        }
}

// ================= bf16 mma implicit-GEMM conv 3x3 s1 p1 — padded 10x10 RAW (R11 champion) ======
template <int CIN, int COUTF, int NSPL, int RING>
__global__ __launch_bounds__(256, 2) void conv_mma(const __nv_bfloat16* __restrict__ in,
                                                   const __nv_bfloat16* __restrict__ wt,
                                                   const float* __restrict__ bias,
                                                   __nv_bfloat16* __restrict__ out) {
    constexpr int CINP = CIN + 8;
    constexpr int CB = CIN / 32, NCH = 9 * CB, ND = NCH / 2;
    constexpr int COUT = COUTF / NSPL;
    constexpr int NW = COUT / 4, NT = NW / 8;
    constexpr int RAWQ = 200 * CINP * 2 / 16;
    extern __shared__ char dynsm[];
    __nv_bfloat16* RAW = (__nv_bfloat16*)dynsm;       // 2 imgs * 100 padded px * CINP
    __nv_bfloat16* BS = RAW + 200 * CINP;             // RING * COUT * 80
    uint32_t rawb = smem_u32(RAW), bsb = smem_u32(BS);
    int tid = threadIdx.x, lane = tid & 31, wid = tid >> 5;
    int mwarp = wid & 1, nwarp = wid >> 1;
    int b0 = blockIdx.x * 2;
    int sl = (NSPL > 1) ? blockIdx.y : 0;

    uint4 z4 = make_uint4(0, 0, 0, 0);
    for (int i = tid; i < RAWQ; i += 256) ((uint4*)RAW)[i] = z4;
    __syncthreads();

    const __nv_bfloat16* inb = in + (size_t)b0 * 64 * CIN;
    constexpr int SEGS = CIN / 8;
    #pragma unroll
    for (int u = 0; u < 128 * SEGS / 256; u++) {
        int i = u * 256 + tid;
        int px = i / SEGS, seg = i % SEGS;
        int img = px >> 6, p = px & 63, oh = p >> 3, ow = p & 7;
        int pad = img * 100 + (oh + 1) * 10 + (ow + 1);
        cp16(rawb + (uint32_t)((pad * CINP + seg * 8) * 2), inb + (size_t)px * CIN + seg * 8);
    }
    auto issueB2 = [&](int i) {
        int t = (2 * i) / CB;
        #pragma unroll
        for (int j = 0; j < 2; j++) {
            int cb = (2 * i + j) % CB;
            const __nv_bfloat16* wb = wt + ((size_t)t * COUTF + sl * COUT) * CIN + cb * 32;
            uint32_t dst = bsb + (uint32_t)(((i % RING) * COUT * 80 + j * COUT * 40) * 2);
            #pragma unroll
            for (int u = 0; u < COUT * 4 / 256; u++) {
                int idx = u * 256 + tid;
                int oc = idx >> 2, seg = idx & 3;
                cp16(dst + (uint32_t)((oc * 40 + seg * 8) * 2), wb + (size_t)oc * CIN + seg * 8);
            }
        }
    };
    issueB2(0); CP_COMMIT();
    if (RING == 3) { issueB2(1); CP_COMMIT(); }

    int tile_r = lane & 15, khalf = lane >> 4;
    uint32_t abase[4];
    #pragma unroll
    for (int mt = 0; mt < 4; mt++) {
        int r = mwarp * 64 + mt * 16 + tile_r;
        int img = r >> 6, px = r & 63, oh = px >> 3, ow = px & 7;
        int pad = img * 100 + (oh + 1) * 10 + (ow + 1);
        abase[mt] = rawb + (uint32_t)((pad * CINP + khalf * 8) * 2);
    }
    int nB = nwarp * NW + (lane & 7);
    int khB = (lane >> 3) & 1;

    float acc[4][NT][4];
    #pragma unroll
    for (int mt = 0; mt < 4; mt++)
        #pragma unroll
        for (int nt = 0; nt < NT; nt++)
            #pragma unroll
            for (int q = 0; q < 4; q++) acc[mt][nt][q] = 0.f;

    for (int i = 0; i < ND; i++) {
        if (RING == 3) { CP_WAIT1(); } else { CP_WAIT0(); }
        __syncthreads();
        if (i + RING - 1 < ND) { issueB2(i + RING - 1); }
        CP_COMMIT();
        int t = (2 * i) / CB;
        int kh = t / 3, kw = t % 3;
        int toff = ((kh - 1) * 10 + (kw - 1)) * CINP * 2;
        #pragma unroll
        for (int j = 0; j < 2; j++) {
            int cb = (2 * i + j) % CB;
            uint32_t aaddr[4];
            #pragma unroll
            for (int mt = 0; mt < 4; mt++)
                aaddr[mt] = (uint32_t)((int)abase[mt] + toff + cb * 64);
            uint32_t bbase = bsb + (uint32_t)(((i % RING) * COUT * 80 + j * COUT * 40) * 2);
            #pragma unroll
            for (int kk = 0; kk < 2; kk++) {
                uint32_t a[4][4];
                #pragma unroll
                for (int mt = 0; mt < 4; mt++) ldsm_x4(a[mt], aaddr[mt] + kk * 32);
                uint32_t b[NT][2];
                #pragma unroll
                for (int nt = 0; nt < NT; nt++)
                    ldsm_x2(b[nt], bbase + (uint32_t)(((nB + nt * 8) * 40 + kk * 16 + khB * 8) * 2));
                #pragma unroll
                for (int mt = 0; mt < 4; mt++)
                    #pragma unroll
                    for (int nt = 0; nt < NT; nt++)
                        mma16(acc[mt][nt], a[mt], b[nt]);
            }
        }
    }
    #pragma unroll
    for (int mt = 0; mt < 4; mt++)
        #pragma unroll
        for (int nt = 0; nt < NT; nt++) {
            int n = nwarp * NW + nt * 8 + (lane & 3) * 2;
            float bv0 = bias[sl * COUT + n], bv1 = bias[sl * COUT + n + 1];
            #pragma unroll
            for (int h = 0; h < 2; h++) {
                int r = mwarp * 64 + mt * 16 + (lane >> 2) + h * 8;
                int img = r >> 6, px = r & 63;
                uint32_t pk = packbf(fmaxf(acc[mt][nt][h * 2 + 0] + bv0, 0.f),
                                     fmaxf(acc[mt][nt][h * 2 + 1] + bv1, 0.f));
                *(uint32_t*)(out + ((size_t)(b0 + img) * 64 + px) * COUTF + sl * COUT + n) = pk;
            }
        }
}

// ================= bf16 mma GEMM: z0 = h4 @ encwT^T, M64 N128 K-chunk 64 (A read 2x not 4x) ====
__global__ __launch_bounds__(256, 2) void enc_mma(const __nv_bfloat16* __restrict__ A,
                                                  const __nv_bfloat16* __restrict__ Bw,
                                                  const float* __restrict__ bias,
                                                  float* __restrict__ C) {
    constexpr int K = 16384, NCH = K / 64;
    extern __shared__ char dynsm[];
    __nv_bfloat16* AS = (__nv_bfloat16*)dynsm;        // 3 * 64*72
    __nv_bfloat16* BSm = AS + 3 * 64 * 72;            // 3 * 128*72
    uint32_t asb = smem_u32(AS), bsb = smem_u32(BSm);
    int tid = threadIdx.x, lane = tid & 31, wid = tid >> 5;
    int mwarp = wid & 1, nwarp = wid >> 1;    // 2 m-warps x 4 n-warps
    int m0 = blockIdx.x * 64, n0 = blockIdx.y * 128;

    auto issue = [&](int j) {
        int buf = j % 3;
        const __nv_bfloat16* Ab = A + (size_t)m0 * K + j * 64;
        const __nv_bfloat16* Bb = Bw + (size_t)n0 * K + j * 64;
        #pragma unroll
        for (int u = 0; u < 2; u++) {
            int i = u * 256 + tid;
            int r = i >> 3, seg = i & 7;
            cp16(asb + (uint32_t)(buf * 64 * 72 + r * 72 + seg * 8) * 2, Ab + (size_t)r * K + seg * 8);
        }
        #pragma unroll
        for (int u = 0; u < 4; u++) {
            int i = u * 256 + tid;
            int r = i >> 3, seg = i & 7;
            cp16(bsb + (uint32_t)(buf * 128 * 72 + r * 72 + seg * 8) * 2, Bb + (size_t)r * K + seg * 8);
        }
    };
    issue(0); CP_COMMIT();
    issue(1); CP_COMMIT();

    int tile_r = lane & 15, khalf = lane >> 4;
    int ra[2];
    #pragma unroll
    for (int mt = 0; mt < 2; mt++) ra[mt] = mwarp * 32 + mt * 16 + tile_r;
    int nB = nwarp * 32 + (lane & 7);    // NW = 32, NT = 4
    int khB = (lane >> 3) & 1;

    float acc[2][4][4];
    #pragma unroll
    for (int mt = 0; mt < 2; mt++)
        #pragma unroll
        for (int nt = 0; nt < 4; nt++)
            #pragma unroll
            for (int q = 0; q < 4; q++) acc[mt][nt][q] = 0.f;

    for (int i = 0; i < NCH; i++) {
        CP_WAIT1();
        __syncthreads();
        if (i + 2 < NCH) { issue(i + 2); }
        CP_COMMIT();
        uint32_t abase = asb + (uint32_t)((i % 3) * 64 * 72 * 2);
        uint32_t bbase = bsb + (uint32_t)((i % 3) * 128 * 72 * 2);
        #pragma unroll
        for (int kk = 0; kk < 4; kk++) {
            uint32_t a[2][4];
            #pragma unroll
            for (int mt = 0; mt < 2; mt++)
                ldsm_x4(a[mt], abase + (uint32_t)((ra[mt] * 72 + kk * 16 + khalf * 8) * 2));
            uint32_t b[4][2];
            #pragma unroll
            for (int nt = 0; nt < 4; nt++)
                ldsm_x2(b[nt], bbase + (uint32_t)(((nB + nt * 8) * 72 + kk * 16 + khB * 8) * 2));
            #pragma unroll
            for (int mt = 0; mt < 2; mt++)
                #pragma unroll
                for (int nt = 0; nt < 4; nt++)
                    mma16(acc[mt][nt], a[mt], b[nt]);
        }
    }
    #pragma unroll
    for (int mt = 0; mt < 2; mt++)
        #pragma unroll
        for (int nt = 0; nt < 4; nt++) {
            int n = n0 + nwarp * 32 + nt * 8 + (lane & 3) * 2;
            float bv0 = bias[n], bv1 = bias[n + 1];
            #pragma unroll
            for (int h = 0; h < 2; h++) {
                int m = m0 + mwarp * 32 + mt * 16 + (lane >> 2) + h * 8;
                float2 o;
                o.x = acc[mt][nt][h * 2 + 0] + bv0;
                o.y = acc[mt][nt][h * 2 + 1] + bv1;
                *(float2*)(C + (size_t)m * 256 + n) = o;
            }
        }
}

// ================= fp32 GEMM (node_fc only) =================
__global__ void gemm_kernel(const float* __restrict__ A, const float* __restrict__ Bm,
                            const float* __restrict__ bias, float* __restrict__ C,
                            int K, int N) {
    __shared__ float As[8][68];
    __shared__ float Bs[8][68];
    int tid = threadIdx.x;
    int row0 = blockIdx.x * 64;
    int col0 = blockIdx.y * 64;
    int tr = tid / 16, tc = tid % 16;
    int ar = tid / 8, ac = tid % 8;
    int br = tid / 64, bc = tid % 64;
    float acc[4][4];
    #pragma unroll
    for (int i = 0; i < 4; i++)
        #pragma unroll
        for (int j = 0; j < 4; j++) acc[i][j] = 0.f;
    for (int k0 = 0; k0 < K; k0 += 8) {
        #pragma unroll
        for (int i = 0; i < 2; i++)
            As[ac][ar + i * 32] = A[(size_t)(row0 + ar + i * 32) * K + k0 + ac];
        #pragma unroll
        for (int i = 0; i < 2; i++)
            Bs[br + i * 4][bc] = Bm[(size_t)(k0 + br + i * 4) * N + col0 + bc];
        __syncthreads();
        #pragma unroll
        for (int kk = 0; kk < 8; kk++) {
            float4 a = *(const float4*)&As[kk][tr * 4];
            float4 b = *(const float4*)&Bs[kk][tc * 4];
            acc[0][0] += a.x * b.x; acc[0][1] += a.x * b.y; acc[0][2] += a.x * b.z; acc[0][3] += a.x * b.w;
            acc[1][0] += a.y * b.x; acc[1][1] += a.y * b.y; acc[1][2] += a.y * b.z; acc[1][3] += a.y * b.w;
            acc[2][0] += a.z * b.x; acc[2][1] += a.z * b.y; acc[2][2] += a.z * b.z; acc[2][3] += a.z * b.w;
            acc[3][0] += a.w * b.x; acc[3][1] += a.w * b.y; acc[3][2] += a.w * b.z; acc[3][3] += a.w * b.w;
        }
        __syncthreads();
    }
    #pragma unroll
    for (int i = 0; i < 4; i++) {
        int r = row0 + tr * 4 + i;
        #pragma unroll
        for (int j = 0; j < 4; j++) {
            int cidx = col0 + tc * 4 + j;
            C[(size_t)r * N + cidx] = acc[i][j] + bias[cidx];
        }
    }
}

// ================= proto distances + softmax/gate + blend + LOGITS (fused) =================
__global__ void proto_kernel(const float* __restrict__ protos,
                             const float* __restrict__ temp_raw,
                             const float* __restrict__ gate,
                             const float* __restrict__ clf_b,
                             float* __restrict__ out) {
    __shared__ float zs[8 * 256];
    __shared__ float dsm[8 * 256];
    __shared__ float wsm[8 * 256];
    __shared__ float zn2[8];
    int b0 = blockIdx.x * 8;
    int tid = threadIdx.x;
    for (int i = tid; i < 2048; i += 256) zs[i] = g_z[(size_t)b0 * 256 + i];
    __syncthreads();
    if (tid < 8) {
        float s = 0.f;
        for (int k = 0; k < 256; k++) { float v = zs[tid * 256 + k]; s += v * v; }
        zn2[tid] = s;
    }
    __syncthreads();
    int j = tid;
    float ap[8], ag[8];
    #pragma unroll
    for (int r = 0; r < 8; r++) { ap[r] = 0.f; ag[r] = 0.f; }
    for (int k = 0; k < 256; k++) {
        float pv = g_protosT[k * 256 + j];
        float gv = g_gridT[k * 256 + j];
        #pragma unroll
        for (int r = 0; r < 8; r++) {
            float zv = zs[r * 256 + k];
            ap[r] += zv * pv;
            ag[r] += zv * gv;
        }
    }
    float pj = g_pn2[j], gj = g_gn2[j];
    #pragma unroll
    for (int r = 0; r < 8; r++) {
        float d1 = sqrtf(fmaxf(zn2[r] + pj - 2.f * ap[r], 0.f));
        float d2 = sqrtf(fmaxf(zn2[r] + gj - 2.f * ag[r], 0.f));
        dsm[r * 256 + j] = d1 + d2;
    }
    __syncthreads();
    float temp = 1.f / (1.f + expf(-temp_raw[0])) * 0.999f + 0.001f;
    float invt = 1.f / temp;
    int wr = tid >> 5;
    int lane = tid & 31;
    float mn = dsm[wr * 256 + lane];
    #pragma unroll
    for (int t = 1; t < 8; t++) mn = fminf(mn, dsm[wr * 256 + lane + t * 32]);
    #pragma unroll
    for (int o = 16; o; o >>= 1) mn = fminf(mn, __shfl_xor_sync(0xffffffffu, mn, o));
    float pvals[8];
    float S = 0.f;
    #pragma unroll
    for (int t = 0; t < 8; t++) {
        float e = expf((mn - dsm[wr * 256 + lane + t * 32]) * invt);
        pvals[t] = e; S += e;
    }
    #pragma unroll
    for (int o = 16; o; o >>= 1) S += __shfl_xor_sync(0xffffffffu, S, o);
    float invS = 1.f / S;
    float T = 0.f;
    #pragma unroll
    for (int t = 0; t < 8; t++) {
        int jj = lane + t * 32;
        float sg = 1.f / (1.f + expf(-gate[jj]));
        float bb = pvals[t] * invS * sg;
        pvals[t] = bb; T += bb;
    }
    #pragma unroll
    for (int o = 16; o; o >>= 1) T += __shfl_xor_sync(0xffffffffu, T, o);
    float inv = 1.f / (T + 1e-8f);
    #pragma unroll
    for (int t = 0; t < 8; t++) wsm[wr * 256 + lane + t * 32] = pvals[t] * inv;
    __syncthreads();
    // blended (reuse dsm as blend buffer)
    int d = tid;
    float accb[8];
    #pragma unroll
    for (int r = 0; r < 8; r++) accb[r] = 0.f;
    for (int jj = 0; jj < 256; jj++) {
        float pv = protos[(size_t)jj * 256 + d];
        #pragma unroll
        for (int r = 0; r < 8; r++) accb[r] += wsm[r * 256 + jj] * pv;
    }
    #pragma unroll
    for (int r = 0; r < 8; r++) dsm[r * 256 + d] = accb[r];
    __syncthreads();
    // fused logits: out[b0+r][c] = clf_b[c] + sum_d blend[r][d]*wsum[d][c]
    if (tid < 80) {
        int r = tid / 10, c = tid % 10;
        float acc = clf_b[c];
        for (int dd = 0; dd < 256; dd++) acc += dsm[r * 256 + dd] * g_wsum[dd * 10 + c];
        out[(size_t)(b0 + r) * 10 + c] = acc;
    }
}

// ================= launch =================
extern "C" void kernel_launch(void* const* d_in, const int* in_sizes, int n_in,
                              void* d_out, int out_size) {
    const float* x        = (const float*)d_in[0];
    const float* conv1_w  = (const float*)d_in[2];
    const float* conv1_b  = (const float*)d_in[3];
    const float* conv2_w  = (const float*)d_in[4];
    const float* conv2_b  = (const float*)d_in[5];
    const float* conv3_w  = (const float*)d_in[6];
    const float* conv3_b  = (const float*)d_in[7];
    const float* conv4_w  = (const float*)d_in[8];
    const float* conv4_b  = (const float*)d_in[9];
    const float* enc_w    = (const float*)d_in[10];
    const float* enc_b    = (const float*)d_in[11];
    const float* clf_w    = (const float*)d_in[18];
    const float* clf_b    = (const float*)d_in[19];
    const float* node_fc_w = (const float*)d_in[20];
    const float* node_fc_b = (const float*)d_in[21];
    const float* protos   = (const float*)d_in[22];
    const float* grid_pos = (const float*)d_in[23];
    const float* temp_raw = (const float*)d_in[24];
    const float* gate     = (const float*)d_in[25];
    float* out = (float*)d_out;

    __nv_bfloat16 *p_h1, *p_h2, *p_h3, *p_h4, *p_encwT, *p_w2t, *p_w3t, *p_w4t;
    float *p_z0, *p_z;
    cudaGetSymbolAddress((void**)&p_h1, g_h1bf);
    cudaGetSymbolAddress((void**)&p_h2, g_h2bf);
    cudaGetSymbolAddress((void**)&p_h3, g_h3bf);
    cudaGetSymbolAddress((void**)&p_h4, g_h4bf);
    cudaGetSymbolAddress((void**)&p_z0, g_z0);
    cudaGetSymbolAddress((void**)&p_z, g_z);
    cudaGetSymbolAddress((void**)&p_encwT, g_encwT);
    cudaGetSymbolAddress((void**)&p_w2t, g_w2t);
    cudaGetSymbolAddress((void**)&p_w3t, g_w3t);
    cudaGetSymbolAddress((void**)&p_w4t, g_w4t);

    // dynamic smem (bytes)
    static const int SM2 = (2 * 289 * 40 + 3 * 64 * 40) * 2;                 // 61600
    static const int SM3 = (200 * 72 + 3 * 128 * 80) * 2;                    // 90240
    static const int SM4 = (200 * 136 + 2 * 128 * 80) * 2;                   // 95360
    static const int SME = (3 * 64 * 72 + 3 * 128 * 72) * 2;                 // 82944
    cudaFuncSetAttribute(conv2_mma, cudaFuncAttributeMaxDynamicSharedMemorySize, SM2);
    cudaFuncSetAttribute(conv_mma<64, 128, 1, 3>, cudaFuncAttributeMaxDynamicSharedMemorySize, SM3);
    cudaFuncSetAttribute(conv_mma<128, 256, 2, 2>, cudaFuncAttributeMaxDynamicSharedMemorySize, SM4);
    cudaFuncSetAttribute(enc_mma, cudaFuncAttributeMaxDynamicSharedMemorySize, SME);

    conv1_kernel<<<B_, 256>>>(x, conv1_w, conv1_b);
    prep_all<<<2281, 256>>>(protos, grid_pos, clf_w, enc_w, conv2_w, conv3_w, conv4_w);

    conv2_mma<<<B_ / 2, 256, SM2>>>(p_h1, p_w2t, conv2_b, p_h2);
    conv_mma<64, 128, 1, 3><<<dim3(B_ / 2, 1), 256, SM3>>>(p_h2, p_w3t, conv3_b, p_h3);
    conv_mma<128, 256, 2, 2><<<dim3(B_ / 2, 2), 256, SM4>>>(p_h3, p_w4t, conv4_b, p_h4);

    enc_mma<<<dim3(64, 2), 256, SME>>>(p_h4, p_encwT, enc_b, p_z0);
    gemm_kernel<<<dim3(64, 4), 256>>>(p_z0, node_fc_w, node_fc_b, p_z, D_, D_);

    proto_kernel<<<B_ / 8, 256>>>(protos, temp_raw, gate, clf_b, out);
}

// round 17
// speedup vs baseline: 1.4650x; 1.4650x over previous
#include <cuda_runtime.h>
#include <cuda_bf16.h>
#include <math.h>
#include <cstdint>

#define B_ 4096
#define D_ 256
#define NPROTO 256

// ---------------- scratch (device globals; no allocations allowed) ----------------
__device__ __nv_bfloat16 g_h1bf[(size_t)B_ * 225 * 32];   // NHWC bf16
__device__ __nv_bfloat16 g_h2bf[(size_t)B_ * 64 * 64];    // NHWC bf16
__device__ __nv_bfloat16 g_h3bf[(size_t)B_ * 64 * 128];   // NHWC bf16
__device__ __nv_bfloat16 g_h4bf[(size_t)B_ * 64 * 256];   // NHWC bf16
__device__ float g_z0[B_ * D_];
__device__ float g_z[B_ * D_];
__device__ float g_protosT[NPROTO * D_];
__device__ float g_gridT[NPROTO * D_];
__device__ float g_pn2[NPROTO];
__device__ float g_gn2[NPROTO];
__device__ float g_wsum[D_ * 10];
__device__ __nv_bfloat16 g_encwT[(size_t)D_ * 16384];   // [d][k], k = p*256+c
__device__ __nv_bfloat16 g_w2t[9 * 64 * 32];            // [tap][oc][c]
__device__ __nv_bfloat16 g_w3t[9 * 128 * 64];
__device__ __nv_bfloat16 g_w4t[9 * 256 * 128];

// ================= helpers =================
__device__ __forceinline__ uint32_t smem_u32(const void* p) {
    uint32_t a;
    asm("{ .reg .u64 t; cvta.to.shared.u64 t, %1; cvt.u32.u64 %0, t; }" : "=r"(a) : "l"(p));
    return a;
}
__device__ __forceinline__ void cp16(uint32_t s, const void* g) {
    asm volatile("cp.async.cg.shared.global [%0], [%1], 16;" :: "r"(s), "l"(g));
}
#define CP_COMMIT() asm volatile("cp.async.commit_group;" ::: "memory")
#define CP_WAIT1()  asm volatile("cp.async.wait_group 1;" ::: "memory")
#define CP_WAIT0()  asm volatile("cp.async.wait_group 0;" ::: "memory")

__device__ __forceinline__ uint32_t packbf(float lo, float hi) {
    uint32_t r; asm("cvt.rn.bf16x2.f32 %0, %1, %2;" : "=r"(r) : "f"(hi), "f"(lo)); return r;
}
__device__ __forceinline__ void mma16(float c[4], const uint32_t a[4], const uint32_t b[2]) {
    asm volatile(
        "mma.sync.aligned.m16n8k16.row.col.f32.bf16.bf16.f32 "
        "{%0,%1,%2,%3}, {%4,%5,%6,%7}, {%8,%9}, {%0,%1,%2,%3};"
        : "+f"(c[0]), "+f"(c[1]), "+f"(c[2]), "+f"(c[3])
        : "r"(a[0]), "r"(a[1]), "r"(a[2]), "r"(a[3]), "r"(b[0]), "r"(b[1]));
}
__device__ __forceinline__ void ldsm_x4(uint32_t r[4], uint32_t addr) {
    asm volatile("ldmatrix.sync.aligned.m8n8.x4.shared.b16 {%0,%1,%2,%3}, [%4];"
        : "=r"(r[0]), "=r"(r[1]), "=r"(r[2]), "=r"(r[3]) : "r"(addr));
}
__device__ __forceinline__ void ldsm_x2(uint32_t r[2], uint32_t addr) {
    asm volatile("ldmatrix.sync.aligned.m8n8.x2.shared.b16 {%0,%1}, [%2];"
        : "=r"(r[0]), "=r"(r[1]) : "r"(addr));
}

// ================= merged prep kernel =================
__global__ void prep_all(const float* __restrict__ protos,
                         const float* __restrict__ grid_pos,
                         const float* __restrict__ clf_w,
                         const float* __restrict__ enc_w,
                         const float* __restrict__ w2,
                         const float* __restrict__ w3,
                         const float* __restrict__ w4) {
    __shared__ float sbuf[32 * 257];
    int bid = blockIdx.x;
    int tid = threadIdx.x;
    if (bid < 256) {
        float pv = protos[bid * D_ + tid];
        float gv = grid_pos[bid * D_ + tid];
        g_protosT[tid * NPROTO + bid] = pv;
        g_gridT[tid * NPROTO + bid] = gv;
        float* red = sbuf;
        red[tid] = pv * pv;
        __syncthreads();
        for (int s = 128; s > 0; s >>= 1) { if (tid < s) red[tid] += red[tid + s]; __syncthreads(); }
        if (tid == 0) g_pn2[bid] = red[0];
        __syncthreads();
        red[tid] = gv * gv;
        __syncthreads();
        for (int s = 128; s > 0; s >>= 1) { if (tid < s) red[tid] += red[tid + s]; __syncthreads(); }
        if (tid == 0) g_gn2[bid] = red[0];
    } else if (bid == 256) {
        for (int i = tid; i < D_ * 10; i += 256) {
            int dd = i / 10, c = i % 10;
            float s = 0.f;
            #pragma unroll
            for (int h = 0; h < 4; h++) s += clf_w[(h * 256 + dd) * 10 + c];
            g_wsum[i] = s;
        }
    } else if (bid < 769) {
        float (*s)[257] = (float (*)[257])sbuf;
        int k0 = (bid - 257) * 32;
        for (int r = 0; r < 32; r++) {
            int k = k0 + r;
            int c = k & 255, p = k >> 8;
            s[r][tid] = enc_w[(size_t)(c * 64 + p) * 256 + tid];
        }
        __syncthreads();
        int lane = tid & 31, w = tid >> 5;
        for (int d = w; d < 256; d += 8)
            g_encwT[(size_t)d * 16384 + k0 + lane] = __float2bfloat16(s[lane][d]);
    } else {
        const float* w; __nv_bfloat16* wt; int COUT, CIN, base;
        if (bid < 841)       { w = w2; wt = g_w2t; COUT = 64;  CIN = 32;  base = 769; }
        else if (bid < 1129) { w = w3; wt = g_w3t; COUT = 128; CIN = 64;  base = 841; }
        else                 { w = w4; wt = g_w4t; COUT = 256; CIN = 128; base = 1129; }
        int i = (bid - base) * 256 + tid;
        if (i < 9 * COUT * CIN) {
            int c = i % CIN;
            int oc = (i / CIN) % COUT;
            int t = i / (CIN * COUT);
            wt[i] = __float2bfloat16(w[((size_t)(oc * CIN + c)) * 9 + t]);
        }
    }
}

// ================= conv1: 3->32, 5x5, s2, p1 — branch-free padded, reg weights =================
__global__ __launch_bounds__(256) void conv1_kernel(const float* __restrict__ x,
                                                    const float* __restrict__ w,
                                                    const float* __restrict__ bias) {
    __shared__ __align__(16) float xs[3 * 34 * 36];
    __shared__ float ws[2400];
    int b = blockIdx.x, tid = threadIdx.x;
    for (int i = tid; i < 3 * 34 * 36; i += 256) xs[i] = 0.f;
    for (int i = tid; i < 2400; i += 256) ws[i] = w[i];
    __syncthreads();
    const float* xb = x + (size_t)b * 3072;
    for (int i = tid; i < 3072; i += 256) {
        int c = i >> 10, rem = i & 1023, ih = rem >> 5, iw = rem & 31;
        xs[c * 1224 + (ih + 1) * 36 + (iw + 1)] = xb[i];
    }
    __syncthreads();
    int oc = tid & 31, wg = tid >> 5;
    float wr[75];
    #pragma unroll
    for (int t = 0; t < 75; t++) wr[t] = ws[oc * 75 + t];
    float bv = bias[oc];
    __nv_bfloat16* ob = g_h1bf + (size_t)b * 225 * 32 + oc;
    for (int oh = wg; oh < 15; oh += 8) {
        float acc[8];
        #pragma unroll
        for (int j = 0; j < 8; j++) acc[j] = bv;
        #pragma unroll
        for (int c = 0; c < 3; c++)
            #pragma unroll
            for (int kh = 0; kh < 5; kh++) {
                const float* row = xs + c * 1224 + (2 * oh + kh) * 36;
                float xv[20];
                #pragma unroll
                for (int q = 0; q < 5; q++) *(float4*)(xv + q * 4) = *(const float4*)(row + q * 4);
                #pragma unroll
                for (int kw = 0; kw < 5; kw++) {
                    float wv = wr[c * 25 + kh * 5 + kw];
                    #pragma unroll
                    for (int ow = 0; ow < 8; ow++) acc[ow] += xv[2 * ow + kw] * wv;
                }
            }
        #pragma unroll
        for (int ow = 0; ow < 8; ow++)
            ob[(size_t)(oh * 15 + ow) * 32] = __float2bfloat16(fmaxf(acc[ow], 0.f));
        float acc2[7];
        #pragma unroll
        for (int j = 0; j < 7; j++) acc2[j] = bv;
        #pragma unroll
        for (int c = 0; c < 3; c++)
            #pragma unroll
            for (int kh = 0; kh < 5; kh++) {
                const float* row = xs + c * 1224 + (2 * oh + kh) * 36 + 16;
                float xv[20];
                #pragma unroll
                for (int q = 0; q < 5; q++) *(float4*)(xv + q * 4) = *(const float4*)(row + q * 4);
                #pragma unroll
                for (int kw = 0; kw < 5; kw++) {
                    float wv = wr[c * 25 + kh * 5 + kw];
                    #pragma unroll
                    for (int j = 0; j < 7; j++) acc2[j] += xv[2 * j + kw] * wv;
                }
            }
        #pragma unroll
        for (int j = 0; j < 7; j++)
            ob[(size_t)(oh * 15 + 8 + j) * 32] = __float2bfloat16(fmaxf(acc2[j], 0.f));
    }
}

// ================= conv2 mma: 32->64, 3x3, s2, p1 — spatially padded 17x17 RAW =================
__global__ __launch_bounds__(256, 2) void conv2_mma(const __nv_bfloat16* __restrict__ in,
                                                    const __nv_bfloat16* __restrict__ wt,
                                                    const float* __restrict__ bias,
                                                    __nv_bfloat16* __restrict__ out) {
    extern __shared__ char dynsm[];
    __nv_bfloat16* RAW = (__nv_bfloat16*)dynsm;            // 2*289*40
    __nv_bfloat16* BS = RAW + 2 * 289 * 40;                // 3*64*40
    uint32_t rawb = smem_u32(RAW), bsb = smem_u32(BS);
    int tid = threadIdx.x, lane = tid & 31, wid = tid >> 5;
    int mwarp = wid & 1, nwarp = wid >> 1;
    int b0 = blockIdx.x * 2;

    uint4 z4 = make_uint4(0, 0, 0, 0);
    for (int i = tid; i < 2890; i += 256) ((uint4*)RAW)[i] = z4;
    __syncthreads();

    const __nv_bfloat16* inb = in + (size_t)b0 * 225 * 32;
    for (int i = tid; i < 1800; i += 256) {
        int img = i / 900, rem = i % 900, px = rem >> 2, seg = rem & 3;
        int ih = px / 15, iw = px % 15;
        int pad = img * 289 + (ih + 1) * 17 + (iw + 1);
        cp16(rawb + (uint32_t)((pad * 40 + seg * 8) * 2),
             inb + (size_t)(img * 225 + px) * 32 + seg * 8);
    }
    auto issueB = [&](int j) {
        int oc = tid >> 2, seg = tid & 3;
        cp16(bsb + (uint32_t)((j % 3) * 64 * 40 + oc * 40 + seg * 8) * 2,
             wt + ((size_t)j * 64 + oc) * 32 + seg * 8);
    };
    issueB(0); CP_COMMIT();
    issueB(1); CP_COMMIT();

    int tile_r = lane & 15, khalf = lane >> 4;
    uint32_t abase[4];
    #pragma unroll
    for (int mt = 0; mt < 4; mt++) {
        int r = mwarp * 64 + mt * 16 + tile_r;
        int img = r >> 6, px = r & 63, oh = px >> 3, ow = px & 7;
        int pad = img * 289 + (2 * oh) * 17 + (2 * ow);
        abase[mt] = rawb + (uint32_t)((pad * 40 + khalf * 8) * 2);
    }
    int nB = nwarp * 16 + (lane & 7);
    int khB = (lane >> 3) & 1;

    float acc[4][2][4];
    #pragma unroll
    for (int mt = 0; mt < 4; mt++)
        #pragma unroll
        for (int nt = 0; nt < 2; nt++)
            #pragma unroll
            for (int q = 0; q < 4; q++) acc[mt][nt][q] = 0.f;

    for (int i = 0; i < 9; i++) {
        CP_WAIT1();
        __syncthreads();
        if (i + 2 < 9) { issueB(i + 2); }
        CP_COMMIT();
        int kh = i / 3, kw = i % 3;
        uint32_t toff = (uint32_t)(((kh * 17 + kw) * 40) * 2);
        uint32_t aaddr[4];
        #pragma unroll
        for (int mt = 0; mt < 4; mt++) aaddr[mt] = abase[mt] + toff;
        uint32_t bbase = bsb + (uint32_t)((i % 3) * 64 * 40 * 2);
        #pragma unroll
        for (int kk = 0; kk < 2; kk++) {
            uint32_t a[4][4];
            #pragma unroll
            for (int mt = 0; mt < 4; mt++) ldsm_x4(a[mt], aaddr[mt] + kk * 32);
            uint32_t b[2][2];
            #pragma unroll
            for (int nt = 0; nt < 2; nt++)
                ldsm_x2(b[nt], bbase + (uint32_t)(((nB + nt * 8) * 40 + kk * 16 + khB * 8) * 2));
            #pragma unroll
            for (int mt = 0; mt < 4; mt++)
                #pragma unroll
                for (int nt = 0; nt < 2; nt++)
                    mma16(acc[mt][nt], a[mt], b[nt]);
        }
    }
    #pragma unroll
    for (int mt = 0; mt < 4; mt++)
        #pragma unroll
        for (int nt = 0; nt < 2; nt++) {
            int n = nwarp * 16 + nt * 8 + (lane & 3) * 2;
            float bv0 = bias[n], bv1 = bias[n + 1];
            #pragma unroll
            for (int h = 0; h < 2; h++) {
                int r = mwarp * 64 + mt * 16 + (lane >> 2) + h * 8;
                int img = r >> 6, px = r & 63;
                uint32_t pk = packbf(fmaxf(acc[mt][nt][h * 2 + 0] + bv0, 0.f),
                                     fmaxf(acc[mt][nt][h * 2 + 1] + bv1, 0.f));
                *(uint32_t*)(out + ((size_t)(b0 + img) * 64 + px) * 64 + n) = pk;
            }
        }
}

// ================= bf16 mma implicit-GEMM conv 3x3 s1 p1 — padded 10x10 RAW (R11 champion) ======
template <int CIN, int COUTF, int NSPL, int RING>
__global__ __launch_bounds__(256, 2) void conv_mma(const __nv_bfloat16* __restrict__ in,
                                                   const __nv_bfloat16* __restrict__ wt,
                                                   const float* __restrict__ bias,
                                                   __nv_bfloat16* __restrict__ out) {
    constexpr int CINP = CIN + 8;
    constexpr int CB = CIN / 32, NCH = 9 * CB, ND = NCH / 2;
    constexpr int COUT = COUTF / NSPL;
    constexpr int NW = COUT / 4, NT = NW / 8;
    constexpr int RAWQ = 200 * CINP * 2 / 16;
    extern __shared__ char dynsm[];
    __nv_bfloat16* RAW = (__nv_bfloat16*)dynsm;       // 2 imgs * 100 padded px * CINP
    __nv_bfloat16* BS = RAW + 200 * CINP;             // RING * COUT * 80
    uint32_t rawb = smem_u32(RAW), bsb = smem_u32(BS);
    int tid = threadIdx.x, lane = tid & 31, wid = tid >> 5;
    int mwarp = wid & 1, nwarp = wid >> 1;
    int b0 = blockIdx.x * 2;
    int sl = (NSPL > 1) ? blockIdx.y : 0;

    uint4 z4 = make_uint4(0, 0, 0, 0);
    for (int i = tid; i < RAWQ; i += 256) ((uint4*)RAW)[i] = z4;
    __syncthreads();

    const __nv_bfloat16* inb = in + (size_t)b0 * 64 * CIN;
    constexpr int SEGS = CIN / 8;
    #pragma unroll
    for (int u = 0; u < 128 * SEGS / 256; u++) {
        int i = u * 256 + tid;
        int px = i / SEGS, seg = i % SEGS;
        int img = px >> 6, p = px & 63, oh = p >> 3, ow = p & 7;
        int pad = img * 100 + (oh + 1) * 10 + (ow + 1);
        cp16(rawb + (uint32_t)((pad * CINP + seg * 8) * 2), inb + (size_t)px * CIN + seg * 8);
    }
    auto issueB2 = [&](int i) {
        int t = (2 * i) / CB;
        #pragma unroll
        for (int j = 0; j < 2; j++) {
            int cb = (2 * i + j) % CB;
            const __nv_bfloat16* wb = wt + ((size_t)t * COUTF + sl * COUT) * CIN + cb * 32;
            uint32_t dst = bsb + (uint32_t)(((i % RING) * COUT * 80 + j * COUT * 40) * 2);
            #pragma unroll
            for (int u = 0; u < COUT * 4 / 256; u++) {
                int idx = u * 256 + tid;
                int oc = idx >> 2, seg = idx & 3;
                cp16(dst + (uint32_t)((oc * 40 + seg * 8) * 2), wb + (size_t)oc * CIN + seg * 8);
            }
        }
    };
    issueB2(0); CP_COMMIT();
    if (RING == 3) { issueB2(1); CP_COMMIT(); }

    int tile_r = lane & 15, khalf = lane >> 4;
    uint32_t abase[4];
    #pragma unroll
    for (int mt = 0; mt < 4; mt++) {
        int r = mwarp * 64 + mt * 16 + tile_r;
        int img = r >> 6, px = r & 63, oh = px >> 3, ow = px & 7;
        int pad = img * 100 + (oh + 1) * 10 + (ow + 1);
        abase[mt] = rawb + (uint32_t)((pad * CINP + khalf * 8) * 2);
    }
    int nB = nwarp * NW + (lane & 7);
    int khB = (lane >> 3) & 1;

    float acc[4][NT][4];
    #pragma unroll
    for (int mt = 0; mt < 4; mt++)
        #pragma unroll
        for (int nt = 0; nt < NT; nt++)
            #pragma unroll
            for (int q = 0; q < 4; q++) acc[mt][nt][q] = 0.f;

    for (int i = 0; i < ND; i++) {
        if (RING == 3) { CP_WAIT1(); } else { CP_WAIT0(); }
        __syncthreads();
        if (i + RING - 1 < ND) { issueB2(i + RING - 1); }
        CP_COMMIT();
        int t = (2 * i) / CB;
        int kh = t / 3, kw = t % 3;
        int toff = ((kh - 1) * 10 + (kw - 1)) * CINP * 2;
        #pragma unroll
        for (int j = 0; j < 2; j++) {
            int cb = (2 * i + j) % CB;
            uint32_t aaddr[4];
            #pragma unroll
            for (int mt = 0; mt < 4; mt++)
                aaddr[mt] = (uint32_t)((int)abase[mt] + toff + cb * 64);
            uint32_t bbase = bsb + (uint32_t)(((i % RING) * COUT * 80 + j * COUT * 40) * 2);
            #pragma unroll
            for (int kk = 0; kk < 2; kk++) {
                uint32_t a[4][4];
                #pragma unroll
                for (int mt = 0; mt < 4; mt++) ldsm_x4(a[mt], aaddr[mt] + kk * 32);
                uint32_t b[NT][2];
                #pragma unroll
                for (int nt = 0; nt < NT; nt++)
                    ldsm_x2(b[nt], bbase + (uint32_t)(((nB + nt * 8) * 40 + kk * 16 + khB * 8) * 2));
                #pragma unroll
                for (int mt = 0; mt < 4; mt++)
                    #pragma unroll
                    for (int nt = 0; nt < NT; nt++)
                        mma16(acc[mt][nt], a[mt], b[nt]);
            }
        }
    }
    #pragma unroll
    for (int mt = 0; mt < 4; mt++)
        #pragma unroll
        for (int nt = 0; nt < NT; nt++) {
            int n = nwarp * NW + nt * 8 + (lane & 3) * 2;
            float bv0 = bias[sl * COUT + n], bv1 = bias[sl * COUT + n + 1];
            #pragma unroll
            for (int h = 0; h < 2; h++) {
                int r = mwarp * 64 + mt * 16 + (lane >> 2) + h * 8;
                int img = r >> 6, px = r & 63;
                uint32_t pk = packbf(fmaxf(acc[mt][nt][h * 2 + 0] + bv0, 0.f),
                                     fmaxf(acc[mt][nt][h * 2 + 1] + bv1, 0.f));
                *(uint32_t*)(out + ((size_t)(b0 + img) * 64 + px) * COUTF + sl * COUT + n) = pk;
            }
        }
}

// ================= bf16 mma GEMM: z0 = h4 @ encwT^T, M64 N128 K-chunk 64 (A read 2x not 4x) ====
__global__ __launch_bounds__(256, 2) void enc_mma(const __nv_bfloat16* __restrict__ A,
                                                  const __nv_bfloat16* __restrict__ Bw,
                                                  const float* __restrict__ bias,
                                                  float* __restrict__ C) {
    constexpr int K = 16384, NCH = K / 64;
    extern __shared__ char dynsm[];
    __nv_bfloat16* AS = (__nv_bfloat16*)dynsm;        // 3 * 64*72
    __nv_bfloat16* BSm = AS + 3 * 64 * 72;            // 3 * 128*72
    uint32_t asb = smem_u32(AS), bsb = smem_u32(BSm);
    int tid = threadIdx.x, lane = tid & 31, wid = tid >> 5;
    int mwarp = wid & 1, nwarp = wid >> 1;    // 2 m-warps x 4 n-warps
    int m0 = blockIdx.x * 64, n0 = blockIdx.y * 128;

    auto issue = [&](int j) {
        int buf = j % 3;
        const __nv_bfloat16* Ab = A + (size_t)m0 * K + j * 64;
        const __nv_bfloat16* Bb = Bw + (size_t)n0 * K + j * 64;
        #pragma unroll
        for (int u = 0; u < 2; u++) {
            int i = u * 256 + tid;
            int r = i >> 3, seg = i & 7;
            cp16(asb + (uint32_t)(buf * 64 * 72 + r * 72 + seg * 8) * 2, Ab + (size_t)r * K + seg * 8);
        }
        #pragma unroll
        for (int u = 0; u < 4; u++) {
            int i = u * 256 + tid;
            int r = i >> 3, seg = i & 7;
            cp16(bsb + (uint32_t)(buf * 128 * 72 + r * 72 + seg * 8) * 2, Bb + (size_t)r * K + seg * 8);
        }
    };
    issue(0); CP_COMMIT();
    issue(1); CP_COMMIT();

    int tile_r = lane & 15, khalf = lane >> 4;
    int ra[2];
    #pragma unroll
    for (int mt = 0; mt < 2; mt++) ra[mt] = mwarp * 32 + mt * 16 + tile_r;
    int nB = nwarp * 32 + (lane & 7);    // NW = 32, NT = 4
    int khB = (lane >> 3) & 1;

    float acc[2][4][4];
    #pragma unroll
    for (int mt = 0; mt < 2; mt++)
        #pragma unroll
        for (int nt = 0; nt < 4; nt++)
            #pragma unroll
            for (int q = 0; q < 4; q++) acc[mt][nt][q] = 0.f;

    for (int i = 0; i < NCH; i++) {
        CP_WAIT1();
        __syncthreads();
        if (i + 2 < NCH) { issue(i + 2); }
        CP_COMMIT();
        uint32_t abase = asb + (uint32_t)((i % 3) * 64 * 72 * 2);
        uint32_t bbase = bsb + (uint32_t)((i % 3) * 128 * 72 * 2);
        #pragma unroll
        for (int kk = 0; kk < 4; kk++) {
            uint32_t a[2][4];
            #pragma unroll
            for (int mt = 0; mt < 2; mt++)
                ldsm_x4(a[mt], abase + (uint32_t)((ra[mt] * 72 + kk * 16 + khalf * 8) * 2));
            uint32_t b[4][2];
            #pragma unroll
            for (int nt = 0; nt < 4; nt++)
                ldsm_x2(b[nt], bbase + (uint32_t)(((nB + nt * 8) * 72 + kk * 16 + khB * 8) * 2));
            #pragma unroll
            for (int mt = 0; mt < 2; mt++)
                #pragma unroll
                for (int nt = 0; nt < 4; nt++)
                    mma16(acc[mt][nt], a[mt], b[nt]);
        }
    }
    #pragma unroll
    for (int mt = 0; mt < 2; mt++)
        #pragma unroll
        for (int nt = 0; nt < 4; nt++) {
            int n = n0 + nwarp * 32 + nt * 8 + (lane & 3) * 2;
            float bv0 = bias[n], bv1 = bias[n + 1];
            #pragma unroll
            for (int h = 0; h < 2; h++) {
                int m = m0 + mwarp * 32 + mt * 16 + (lane >> 2) + h * 8;
                float2 o;
                o.x = acc[mt][nt][h * 2 + 0] + bv0;
                o.y = acc[mt][nt][h * 2 + 1] + bv1;
                *(float2*)(C + (size_t)m * 256 + n) = o;
            }
        }
}

// ================= fp32 GEMM (node_fc only) =================
__global__ void gemm_kernel(const float* __restrict__ A, const float* __restrict__ Bm,
                            const float* __restrict__ bias, float* __restrict__ C,
                            int K, int N) {
    __shared__ float As[8][68];
    __shared__ float Bs[8][68];
    int tid = threadIdx.x;
    int row0 = blockIdx.x * 64;
    int col0 = blockIdx.y * 64;
    int tr = tid / 16, tc = tid % 16;
    int ar = tid / 8, ac = tid % 8;
    int br = tid / 64, bc = tid % 64;
    float acc[4][4];
    #pragma unroll
    for (int i = 0; i < 4; i++)
        #pragma unroll
        for (int j = 0; j < 4; j++) acc[i][j] = 0.f;
    for (int k0 = 0; k0 < K; k0 += 8) {
        #pragma unroll
        for (int i = 0; i < 2; i++)
            As[ac][ar + i * 32] = A[(size_t)(row0 + ar + i * 32) * K + k0 + ac];
        #pragma unroll
        for (int i = 0; i < 2; i++)
            Bs[br + i * 4][bc] = Bm[(size_t)(k0 + br + i * 4) * N + col0 + bc];
        __syncthreads();
        #pragma unroll
        for (int kk = 0; kk < 8; kk++) {
            float4 a = *(const float4*)&As[kk][tr * 4];
            float4 b = *(const float4*)&Bs[kk][tc * 4];
            acc[0][0] += a.x * b.x; acc[0][1] += a.x * b.y; acc[0][2] += a.x * b.z; acc[0][3] += a.x * b.w;
            acc[1][0] += a.y * b.x; acc[1][1] += a.y * b.y; acc[1][2] += a.y * b.z; acc[1][3] += a.y * b.w;
            acc[2][0] += a.z * b.x; acc[2][1] += a.z * b.y; acc[2][2] += a.z * b.z; acc[2][3] += a.z * b.w;
            acc[3][0] += a.w * b.x; acc[3][1] += a.w * b.y; acc[3][2] += a.w * b.z; acc[3][3] += a.w * b.w;
        }
        __syncthreads();
    }
    #pragma unroll
    for (int i = 0; i < 4; i++) {
        int r = row0 + tr * 4 + i;
        #pragma unroll
        for (int j = 0; j < 4; j++) {
            int cidx = col0 + tc * 4 + j;
            C[(size_t)r * N + cidx] = acc[i][j] + bias[cidx];
        }
    }
}

// ================= proto distances + softmax/gate + blend + LOGITS (fused) =================
__global__ void proto_kernel(const float* __restrict__ protos,
                             const float* __restrict__ temp_raw,
                             const float* __restrict__ gate,
                             const float* __restrict__ clf_b,
                             float* __restrict__ out) {
    __shared__ float zs[8 * 256];
    __shared__ float dsm[8 * 256];
    __shared__ float wsm[8 * 256];
    __shared__ float zn2[8];
    int b0 = blockIdx.x * 8;
    int tid = threadIdx.x;
    for (int i = tid; i < 2048; i += 256) zs[i] = g_z[(size_t)b0 * 256 + i];
    __syncthreads();
    if (tid < 8) {
        float s = 0.f;
        for (int k = 0; k < 256; k++) { float v = zs[tid * 256 + k]; s += v * v; }
        zn2[tid] = s;
    }
    __syncthreads();
    int j = tid;
    float ap[8], ag[8];
    #pragma unroll
    for (int r = 0; r < 8; r++) { ap[r] = 0.f; ag[r] = 0.f; }
    for (int k = 0; k < 256; k++) {
        float pv = g_protosT[k * 256 + j];
        float gv = g_gridT[k * 256 + j];
        #pragma unroll
        for (int r = 0; r < 8; r++) {
            float zv = zs[r * 256 + k];
            ap[r] += zv * pv;
            ag[r] += zv * gv;
        }
    }
    float pj = g_pn2[j], gj = g_gn2[j];
    #pragma unroll
    for (int r = 0; r < 8; r++) {
        float d1 = sqrtf(fmaxf(zn2[r] + pj - 2.f * ap[r], 0.f));
        float d2 = sqrtf(fmaxf(zn2[r] + gj - 2.f * ag[r], 0.f));
        dsm[r * 256 + j] = d1 + d2;
    }
    __syncthreads();
    float temp = 1.f / (1.f + expf(-temp_raw[0])) * 0.999f + 0.001f;
    float invt = 1.f / temp;
    int wr = tid >> 5;
    int lane = tid & 31;
    float mn = dsm[wr * 256 + lane];
    #pragma unroll
    for (int t = 1; t < 8; t++) mn = fminf(mn, dsm[wr * 256 + lane + t * 32]);
    #pragma unroll
    for (int o = 16; o; o >>= 1) mn = fminf(mn, __shfl_xor_sync(0xffffffffu, mn, o));
    float pvals[8];
    float S = 0.f;
    #pragma unroll
    for (int t = 0; t < 8; t++) {
        float e = expf((mn - dsm[wr * 256 + lane + t * 32]) * invt);
        pvals[t] = e; S += e;
    }
    #pragma unroll
    for (int o = 16; o; o >>= 1) S += __shfl_xor_sync(0xffffffffu, S, o);
    float invS = 1.f / S;
    float T = 0.f;
    #pragma unroll
    for (int t = 0; t < 8; t++) {
        int jj = lane + t * 32;
        float sg = 1.f / (1.f + expf(-gate[jj]));
        float bb = pvals[t] * invS * sg;
        pvals[t] = bb; T += bb;
    }
    #pragma unroll
    for (int o = 16; o; o >>= 1) T += __shfl_xor_sync(0xffffffffu, T, o);
    float inv = 1.f / (T + 1e-8f);
    #pragma unroll
    for (int t = 0; t < 8; t++) wsm[wr * 256 + lane + t * 32] = pvals[t] * inv;
    __syncthreads();
    // blended (reuse dsm as blend buffer)
    int d = tid;
    float accb[8];
    #pragma unroll
    for (int r = 0; r < 8; r++) accb[r] = 0.f;
    for (int jj = 0; jj < 256; jj++) {
        float pv = protos[(size_t)jj * 256 + d];
        #pragma unroll
        for (int r = 0; r < 8; r++) accb[r] += wsm[r * 256 + jj] * pv;
    }
    #pragma unroll
    for (int r = 0; r < 8; r++) dsm[r * 256 + d] = accb[r];
    __syncthreads();
    // fused logits: out[b0+r][c] = clf_b[c] + sum_d blend[r][d]*wsum[d][c]
    if (tid < 80) {
        int r = tid / 10, c = tid % 10;
        float acc = clf_b[c];
        for (int dd = 0; dd < 256; dd++) acc += dsm[r * 256 + dd] * g_wsum[dd * 10 + c];
        out[(size_t)(b0 + r) * 10 + c] = acc;
    }
}

// ================= launch =================
extern "C" void kernel_launch(void* const* d_in, const int* in_sizes, int n_in,
                              void* d_out, int out_size) {
    const float* x        = (const float*)d_in[0];
    const float* conv1_w  = (const float*)d_in[2];
    const float* conv1_b  = (const float*)d_in[3];
    const float* conv2_w  = (const float*)d_in[4];
    const float* conv2_b  = (const float*)d_in[5];
    const float* conv3_w  = (const float*)d_in[6];
    const float* conv3_b  = (const float*)d_in[7];
    const float* conv4_w  = (const float*)d_in[8];
    const float* conv4_b  = (const float*)d_in[9];
    const float* enc_w    = (const float*)d_in[10];
    const float* enc_b    = (const float*)d_in[11];
    const float* clf_w    = (const float*)d_in[18];
    const float* clf_b    = (const float*)d_in[19];
    const float* node_fc_w = (const float*)d_in[20];
    const float* node_fc_b = (const float*)d_in[21];
    const float* protos   = (const float*)d_in[22];
    const float* grid_pos = (const float*)d_in[23];
    const float* temp_raw = (const float*)d_in[24];
    const float* gate     = (const float*)d_in[25];
    float* out = (float*)d_out;

    __nv_bfloat16 *p_h1, *p_h2, *p_h3, *p_h4, *p_encwT, *p_w2t, *p_w3t, *p_w4t;
    float *p_z0, *p_z;
    cudaGetSymbolAddress((void**)&p_h1, g_h1bf);
    cudaGetSymbolAddress((void**)&p_h2, g_h2bf);
    cudaGetSymbolAddress((void**)&p_h3, g_h3bf);
    cudaGetSymbolAddress((void**)&p_h4, g_h4bf);
    cudaGetSymbolAddress((void**)&p_z0, g_z0);
    cudaGetSymbolAddress((void**)&p_z, g_z);
    cudaGetSymbolAddress((void**)&p_encwT, g_encwT);
    cudaGetSymbolAddress((void**)&p_w2t, g_w2t);
    cudaGetSymbolAddress((void**)&p_w3t, g_w3t);
    cudaGetSymbolAddress((void**)&p_w4t, g_w4t);

    // dynamic smem (bytes)
    static const int SM2 = (2 * 289 * 40 + 3 * 64 * 40) * 2;                 // 61600
    static const int SM3 = (200 * 72 + 3 * 128 * 80) * 2;                    // 90240
    static const int SM4 = (200 * 136 + 2 * 128 * 80) * 2;                   // 95360
    static const int SME = (3 * 64 * 72 + 3 * 128 * 72) * 2;                 // 82944
    cudaFuncSetAttribute(conv2_mma, cudaFuncAttributeMaxDynamicSharedMemorySize, SM2);
    cudaFuncSetAttribute(conv_mma<64, 128, 1, 3>, cudaFuncAttributeMaxDynamicSharedMemorySize, SM3);
    cudaFuncSetAttribute(conv_mma<128, 256, 2, 2>, cudaFuncAttributeMaxDynamicSharedMemorySize, SM4);
    cudaFuncSetAttribute(enc_mma, cudaFuncAttributeMaxDynamicSharedMemorySize, SME);

    conv1_kernel<<<B_, 256>>>(x, conv1_w, conv1_b);
    prep_all<<<2281, 256>>>(protos, grid_pos, clf_w, enc_w, conv2_w, conv3_w, conv4_w);

    conv2_mma<<<B_ / 2, 256, SM2>>>(p_h1, p_w2t, conv2_b, p_h2);
    conv_mma<64, 128, 1, 3><<<dim3(B_ / 2, 1), 256, SM3>>>(p_h2, p_w3t, conv3_b, p_h3);
    conv_mma<128, 256, 2, 2><<<dim3(B_ / 2, 2), 256, SM4>>>(p_h3, p_w4t, conv4_b, p_h4);

    enc_mma<<<dim3(64, 2), 256, SME>>>(p_h4, p_encwT, enc_b, p_z0);
    gemm_kernel<<<dim3(64, 4), 256>>>(p_z0, node_fc_w, node_fc_b, p_z, D_, D_);

    proto_kernel<<<B_ / 8, 256>>>(protos, temp_raw, gate, clf_b, out);
}